// round 16
// baseline (speedup 1.0000x reference)
#include <cuda_runtime.h>

#define ULL unsigned long long

// ---------- packed f32x2 helpers ----------
__device__ __forceinline__ void fma2(ULL &acc, ULL a, ULL b) {
    asm("fma.rn.f32x2 %0, %1, %2, %0;" : "+l"(acc) : "l"(a), "l"(b));
}
__device__ __forceinline__ ULL add2(ULL a, ULL b) {
    ULL r; asm("add.rn.f32x2 %0, %1, %2;" : "=l"(r) : "l"(a), "l"(b)); return r;
}
__device__ __forceinline__ float2 unpack2(ULL v) {
    float2 r; asm("mov.b64 {%0, %1}, %2;" : "=f"(r.x), "=f"(r.y) : "l"(v)); return r;
}
__device__ __forceinline__ ULL pack2(float x, float y) {
    ULL r; asm("mov.b64 %0, {%1, %2};" : "=l"(r) : "f"(x), "f"(y)); return r;
}

// ---------- problem dims ----------
#define MM 16
#define NN 4096
#define HH 32
#define DD 128
#define PP 8192
#define PTOT (PP + MM)
#define KSPLIT 8
#define PCH 256
#define NPCH 33                 // attno chunks of 256
#define NSCH 65                 // score chunks of 128
#define PSTR (NPCH * PCH)       // 8448

// ---------- device scratch ----------
__device__ float g_invr[MM];
__device__ ULL   g_xn2[NN * 8];                   // [k][mp] m-pair-packed xnorm
__device__ float g_part[KSPLIT * 3 * MM * NN];
__device__ float g_q[MM * NN];
__device__ float g_k[MM * NN];
__device__ float g_v[MM * NN];
__device__ float g_sexp[HH * PSTR * MM];          // [h][p][m]
__device__ float g_nump[NPCH * HH * MM * DD];
__device__ float g_denp[NSCH * HH * MM];

// shared inner step: acc[mp] += dup(kv) * pair[mp],  8 fma2, 4 LDS.128 (broadcast)
__device__ __forceinline__ void kstep(ULL* acc, const ULL* qr, float kv) {
    ULL kd = pack2(kv, kv);
    ulonglong2 a = *(const ulonglong2*)(qr);
    ulonglong2 b = *(const ulonglong2*)(qr + 2);
    ulonglong2 c = *(const ulonglong2*)(qr + 4);
    ulonglong2 d = *(const ulonglong2*)(qr + 6);
    fma2(acc[0], kd, a.x); fma2(acc[1], kd, a.y);
    fma2(acc[2], kd, b.x); fma2(acc[3], kd, b.y);
    fma2(acc[4], kd, c.x); fma2(acc[5], kd, c.y);
    fma2(acc[6], kd, d.x); fma2(acc[7], kd, d.y);
}

// ============================================================
// K1: per-row inverse RMS
// ============================================================
__global__ __launch_bounds__(256) void rms_kernel(const float* __restrict__ X) {
    int m = blockIdx.x;
    int t = threadIdx.x;
    float s = 0.f;
    const float4* Xr = (const float4*)(X + m * NN);
    for (int i = t; i < NN / 4; i += 256) {
        float4 v = Xr[i];
        s += v.x * v.x + v.y * v.y + v.z * v.z + v.w * v.w;
    }
    __shared__ float red[8];
    for (int o = 16; o; o >>= 1) s += __shfl_xor_sync(0xffffffffu, s, o);
    if ((t & 31) == 0) red[t >> 5] = s;
    __syncthreads();
    if (t == 0) {
        float tot = 0.f;
        #pragma unroll
        for (int i = 0; i < 8; i++) tot += red[i];
        g_invr[m] = rsqrtf(tot * (1.0f / (float)NN));
    }
}

// ============================================================
// K1b: build m-pair-packed normalized x:  g_xn2[k][mp]
// ============================================================
__global__ __launch_bounds__(256) void xnorm2_kernel(const float* __restrict__ X) {
    __shared__ float xs[MM][256];
    int kb = blockIdx.x * 256;
    int t = threadIdx.x;
    #pragma unroll
    for (int i = 0; i < 4; i++) {
        int idx = t + i * 256;
        int m = idx >> 6, c = idx & 63;
        float4 v = *(const float4*)(X + m * NN + kb + c * 4);
        float sc = g_invr[m];
        v.x *= sc; v.y *= sc; v.z *= sc; v.w *= sc;
        *(float4*)&xs[m][c * 4] = v;
    }
    __syncthreads();
    ULL* dst = g_xn2 + (size_t)(kb + t) * 8;
    #pragma unroll
    for (int i = 0; i < 8; i++)
        dst[i] = pack2(xs[2 * i][t], xs[2 * i + 1][t]);
}

// ============================================================
// K2: QKV projection, gmem-stream design. grid 768 = 8 ksplit x 96.
// Thread owns column j; streams W[j][k-range] from gmem; x broadcast
// from smem (staged once). Zero inner barriers.
// ============================================================
__global__ __launch_bounds__(128) void qkv_kernel(
    const float* __restrict__ Wq,
    const float* __restrict__ Wk,
    const float* __restrict__ Wv)
{
    __shared__ __align__(16) ULL xt[512][8];   // 32KB x tile for this k-range

    int bid = blockIdx.x;
    int ks = bid / 96;
    int g  = bid % 96;
    int sel = g >> 5;
    int jb  = (g & 31) << 7;
    const float* W = (sel == 0) ? Wq : (sel == 1) ? Wk : Wv;
    int kb = ks << 9;                  // *512

    int t = threadIdx.x;
    // stage x tile: 2048 ulonglong2, coalesced
    {
        const ulonglong2* src = (const ulonglong2*)(g_xn2 + (size_t)kb * 8);
        ulonglong2* dst = (ulonglong2*)&xt[0][0];
        #pragma unroll
        for (int i = 0; i < 16; i++) {
            int off = i * 128 + t;
            dst[off] = src[off];
        }
    }
    __syncthreads();

    int j = jb + t;
    const float4* rp = (const float4*)(W + (size_t)j * NN + kb);

    ULL acc[8];
    #pragma unroll
    for (int i = 0; i < 8; i++) acc[i] = 0ull;

    float4 ka = rp[0], kb4 = rp[1];
    for (int k8 = 0; k8 < 64; k8++) {
        float4 na, nb;
        if (k8 < 63) { na = rp[2 * k8 + 2]; nb = rp[2 * k8 + 3]; }
        const ULL* qr = &xt[k8 * 8][0];
        kstep(acc, qr,      ka.x); kstep(acc, qr + 8,  ka.y);
        kstep(acc, qr + 16, ka.z); kstep(acc, qr + 24, ka.w);
        kstep(acc, qr + 32, kb4.x); kstep(acc, qr + 40, kb4.y);
        kstep(acc, qr + 48, kb4.z); kstep(acc, qr + 56, kb4.w);
        ka = na; kb4 = nb;
    }

    float* dst = g_part + ((size_t)ks * 3 + sel) * (MM * NN) + j;
    #pragma unroll
    for (int mp = 0; mp < 8; mp++) {
        float2 f = unpack2(acc[mp]);
        dst[(2 * mp) * NN]     = f.x;
        dst[(2 * mp + 1) * NN] = f.y;
    }
}

// ============================================================
// K2b: combine k-split partials -> g_q / g_k / g_v
// ============================================================
__global__ __launch_bounds__(256) void combine_kernel() {
    int idx = blockIdx.x * 256 + threadIdx.x;
    int sel = idx >> 16, r = idx & 65535;
    float v = 0.f;
    #pragma unroll
    for (int c = 0; c < KSPLIT; c++)
        v += g_part[((size_t)c * 3 + sel) * 65536 + r];
    float* o = (sel == 0) ? g_q : (sel == 1) ? g_k : g_v;
    o[r] = v;
}

// ============================================================
// K3a: score kernel v3. grid (65, 32), 128 thr. Thread owns p.
// K row streamed from gmem; q m-pair-packed broadcast from smem
// (uniform reads -> no padding needed, rows 64B, 16B-aligned).
// Zero inner barriers. den via end-of-kernel butterfly.
// ============================================================
__global__ __launch_bounds__(128) void score_kernel(const float* __restrict__ cacheK) {
    __shared__ float qraw[MM][128];                // 8KB
    __shared__ __align__(16) ULL q2[128][8];       // 8KB, [k][mp]
    __shared__ ULL dsm[4][8];

    int chunk = blockIdx.x, h = blockIdx.y;
    int t = threadIdx.x, w = t >> 5, lane = t & 31;

    #pragma unroll
    for (int i = 0; i < 4; i++) {
        int idx = t + i * 128;
        int m = idx >> 5, c = idx & 31;
        *(float4*)&qraw[m][c * 4] = *(const float4*)(g_q + m * NN + h * DD + c * 4);
    }
    __syncthreads();
    #pragma unroll
    for (int i = 0; i < 8; i++)
        q2[t][i] = pack2(qraw[2 * i][t], qraw[2 * i + 1][t]);
    __syncthreads();

    int p = chunk * 128 + t;
    bool active = (p < PTOT);

    ULL acc[8];
    #pragma unroll
    for (int i = 0; i < 8; i++) acc[i] = 0ull;

    if (active) {
        const float* base = (p < PP)
            ? (cacheK + ((size_t)h * PP + p) * DD)
            : (g_k + (size_t)(p - PP) * NN + h * DD);
        const float4* rp = (const float4*)base;

        float4 ka = rp[0], kb = rp[1];
        for (int k8 = 0; k8 < 16; k8++) {
            float4 na, nb;
            if (k8 < 15) { na = rp[2 * k8 + 2]; nb = rp[2 * k8 + 3]; }
            const ULL* qr = &q2[k8 * 8][0];
            kstep(acc, qr,      ka.x); kstep(acc, qr + 8,  ka.y);
            kstep(acc, qr + 16, ka.z); kstep(acc, qr + 24, ka.w);
            kstep(acc, qr + 32, kb.x); kstep(acc, qr + 40, kb.y);
            kstep(acc, qr + 48, kb.z); kstep(acc, qr + 56, kb.w);
            ka = na; kb = nb;
        }
    }

    // exp + write scores + den pairs
    ULL dp[8];
    float e[16];
    #pragma unroll
    for (int mp = 0; mp < 8; mp++) {
        float2 f = unpack2(acc[mp]);
        float e0 = active ? __expf(f.x) : 0.f;
        float e1 = active ? __expf(f.y) : 0.f;
        e[2 * mp] = e0; e[2 * mp + 1] = e1;
        dp[mp] = pack2(e0, e1);
    }
    if (active) {
        float* sp = g_sexp + ((size_t)h * PSTR + p) * MM;
        #pragma unroll
        for (int i = 0; i < 4; i++)
            *(float4*)(sp + i * 4) = make_float4(e[4 * i], e[4 * i + 1], e[4 * i + 2], e[4 * i + 3]);
    }

    // den: butterfly across warp, then 4-warp combine
    #pragma unroll
    for (int o = 16; o; o >>= 1) {
        #pragma unroll
        for (int mp = 0; mp < 8; mp++)
            dp[mp] = add2(dp[mp], __shfl_xor_sync(0xffffffffu, dp[mp], o));
    }
    if (lane < 8) dsm[w][lane] = dp[lane];
    __syncthreads();
    if (t < 8) {
        ULL s = add2(add2(dsm[0][t], dsm[1][t]), add2(dsm[2][t], dsm[3][t]));
        float2 f = unpack2(s);
        float* dd = g_denp + ((size_t)chunk * HH + h) * MM;
        dd[2 * t] = f.x; dd[2 * t + 1] = f.y;
    }
}

// ============================================================
// K3b: O kernel v2. grid (33, 32), 128 thr. ulonglong2 score reads
// (1:4 wf:fma). Exchange buffer unioned into es2. Zero inner barriers.
// ============================================================
__global__ __launch_bounds__(128, 7) void attno_kernel(const float* __restrict__ cacheV) {
    __shared__ __align__(16) ULL es2[PCH][MM];     // 32KB; reused as exchange

    int chunk = blockIdx.x, h = blockIdx.y;
    int t = threadIdx.x, w = t >> 5, lane = t & 31;
    int pg2 = w & 1, mg = w >> 1;
    int pbase = chunk * PCH;

    // stage + duplicate scores
    {
        const float* src = g_sexp + ((size_t)h * PSTR + pbase) * MM;
        ULL* e2 = &es2[0][0];
        #pragma unroll
        for (int i = 0; i < 8; i++) {
            int idx = i * 128 + t;
            float4 v = *(const float4*)(src + idx * 4);
            e2[idx * 4 + 0] = pack2(v.x, v.x);
            e2[idx * 4 + 1] = pack2(v.y, v.y);
            e2[idx * 4 + 2] = pack2(v.z, v.z);
            e2[idx * 4 + 3] = pack2(v.w, v.w);
        }
    }
    __syncthreads();

    ULL oa[16];
    #pragma unroll
    for (int i = 0; i < 16; i++) oa[i] = 0ull;

    int npw = (chunk < NPCH - 1) ? 128 : (pg2 ? 0 : 16);
    const float* vrow;
    size_t vstep;
    if (pbase < PP) {
        vrow = cacheV + ((size_t)h * PP + pbase + pg2 * 128) * DD + lane * 4;
        vstep = DD;
    } else {
        vrow = g_v + (size_t)(pbase - PP) * NN + h * DD + lane * 4;
        vstep = NN;
    }

    #pragma unroll 2
    for (int pp = 0; pp < npw; pp++) {
        int p = pg2 * 128 + pp;
        ulonglong2 vv = *(const ulonglong2*)(vrow + (size_t)pp * vstep);
        const ULL* er = &es2[p][mg * 8];
        ulonglong2 s0 = *(const ulonglong2*)(er);
        ulonglong2 s1 = *(const ulonglong2*)(er + 2);
        ulonglong2 s2 = *(const ulonglong2*)(er + 4);
        ulonglong2 s3 = *(const ulonglong2*)(er + 6);
        fma2(oa[0],  vv.x, s0.x); fma2(oa[1],  vv.y, s0.x);
        fma2(oa[2],  vv.x, s0.y); fma2(oa[3],  vv.y, s0.y);
        fma2(oa[4],  vv.x, s1.x); fma2(oa[5],  vv.y, s1.x);
        fma2(oa[6],  vv.x, s1.y); fma2(oa[7],  vv.y, s1.y);
        fma2(oa[8],  vv.x, s2.x); fma2(oa[9],  vv.y, s2.x);
        fma2(oa[10], vv.x, s2.y); fma2(oa[11], vv.y, s2.y);
        fma2(oa[12], vv.x, s3.x); fma2(oa[13], vv.y, s3.x);
        fma2(oa[14], vv.x, s3.y); fma2(oa[15], vv.y, s3.y);
    }

    __syncthreads();                   // all warps done reading es2
    ULL* ox = &es2[0][0];              // reuse as exchange (8KB needed)
    if (pg2 == 1) {
        #pragma unroll
        for (int mi = 0; mi < 8; mi++) {
            ulonglong2 v;
            v.x = oa[2 * mi]; v.y = oa[2 * mi + 1];
            *(ulonglong2*)&ox[((mg * 8 + mi) * 32 + lane) * 2] = v;
        }
    }
    __syncthreads();
    if (pg2 == 0) {
        float* np = g_nump + (((size_t)chunk * HH + h) * MM + mg * 8) * DD + lane * 4;
        #pragma unroll
        for (int mi = 0; mi < 8; mi++) {
            ulonglong2 pv = *(const ulonglong2*)&ox[((mg * 8 + mi) * 32 + lane) * 2];
            ULL r0 = add2(oa[2 * mi], pv.x);
            ULL r1 = add2(oa[2 * mi + 1], pv.y);
            float2 lo = unpack2(r0), hi = unpack2(r1);
            *(float4*)(np + mi * DD) = make_float4(lo.x, lo.y, hi.x, hi.y);
        }
    }
}

// ============================================================
// K4: combine partials, divide, write output [M, N]
// ============================================================
__global__ __launch_bounds__(256) void final_kernel(float* __restrict__ out) {
    int idx = blockIdx.x * 256 + threadIdx.x;
    int m = idx >> 12;
    int hd = idx & 4095;
    int h = hd >> 7, d = hd & 127;
    float num = 0.f, den = 0.f;
    #pragma unroll
    for (int c = 0; c < NPCH; c++)
        num += g_nump[(((size_t)c * HH + h) * MM + m) * DD + d];
    #pragma unroll
    for (int c = 0; c < NSCH; c++)
        den += g_denp[((size_t)c * HH + h) * MM + m];
    out[idx] = num / den;
}

// ============================================================
extern "C" void kernel_launch(void* const* d_in, const int* in_sizes, int n_in,
                              void* d_out, int out_size) {
    const float* X  = (const float*)d_in[0];
    const float* Wq = (const float*)d_in[1];
    const float* Wk = (const float*)d_in[2];
    const float* Wv = (const float*)d_in[3];
    const float* cK = (const float*)d_in[4];
    const float* cV = (const float*)d_in[5];
    float* out = (float*)d_out;

    rms_kernel<<<MM, 256>>>(X);
    xnorm2_kernel<<<16, 256>>>(X);
    qkv_kernel<<<768, 128>>>(Wq, Wk, Wv);
    combine_kernel<<<768, 256>>>();
    score_kernel<<<dim3(NSCH, HH, 1), 128>>>(cK);
    attno_kernel<<<dim3(NPCH, HH, 1), 128>>>(cV);
    final_kernel<<<(MM * NN) / 256, 256>>>(out);
}